// round 1
// baseline (speedup 1.0000x reference)
#include <cuda_runtime.h>
#include <cuda_bf16.h>
#include <mma.h>

using namespace nvcuda;

// ---------------- problem constants ----------------
#define BB      8
#define CDIM    128
#define HH      112
#define WW      112
#define LTOK    (HH*WW)          // 12544
#define MTOK    (BB*LTOK)        // 100352
#define WS      7
#define NTOK    (WS*WS)          // 49
#define NWH     16               // windows per side
#define NWIN_B  (NWH*NWH)        // 256 per batch
#define NWIN    (BB*NWIN_B)      // 2048
#define HEADS   4
#define HD      32
#define SHIFT   3
#define MLP     512

// ---------------- scratch (device globals, no allocation) ----------------
__device__ float          g_xt[(size_t)MTOK*CDIM];      // token-major input (shortcut)
__device__ __nv_bfloat16  g_xw[(size_t)MTOK*CDIM];      // LN1 + windowed (bf16 GEMM A)
__device__ float          g_qkv[(size_t)MTOK*3*CDIM];   // QKV output
__device__ __nv_bfloat16  g_attnout[(size_t)MTOK*CDIM]; // attention out (window order)
__device__ float          g_pout[(size_t)MTOK*CDIM];    // proj out (window order)
__device__ float          g_y[(size_t)MTOK*CDIM];       // residual 1 (token order)
__device__ __nv_bfloat16  g_h[(size_t)MTOK*CDIM];       // LN2 out
__device__ __nv_bfloat16  g_hh[(size_t)MTOK*MLP];       // gelu(fc1) out
__device__ float          g_z[(size_t)MTOK*CDIM];       // final token-major

__device__ __nv_bfloat16  g_wqkv[CDIM*3*CDIM];
__device__ __nv_bfloat16  g_wproj[CDIM*CDIM];
__device__ __nv_bfloat16  g_wfc1[CDIM*MLP];
__device__ __nv_bfloat16  g_wfc2[MLP*CDIM];

// ---------------- helpers ----------------
__device__ __forceinline__ float warp_sum(float v) {
#pragma unroll
    for (int o = 16; o; o >>= 1) v += __shfl_xor_sync(0xffffffffu, v, o);
    return v;
}

// window-order row index -> token index (same mapping forward and reverse)
__device__ __forceinline__ int winrow_to_token(int i) {
    int win = i / NTOK, n = i - win * NTOK;
    int b   = win >> 8;
    int wr  = win & 255;
    int wi  = wr >> 4, wj = wr & 15;
    int r   = n / WS,  c = n - r * WS;
    int hs  = wi * WS + r + SHIFT; if (hs >= HH) hs -= HH;
    int ws_ = wj * WS + c + SHIFT; if (ws_ >= WW) ws_ -= WW;
    return b * LTOK + hs * WW + ws_;
}

__device__ __forceinline__ void store_bf16x4(__nv_bfloat16* p, float a, float b, float c, float d) {
    __nv_bfloat162 p0 = __floats2bfloat162_rn(a, b);
    __nv_bfloat162 p1 = __floats2bfloat162_rn(c, d);
    uint2 u;
    u.x = *reinterpret_cast<unsigned*>(&p0);
    u.y = *reinterpret_cast<unsigned*>(&p1);
    *reinterpret_cast<uint2*>(p) = u;
}

// ---------------- weight convert ----------------
__global__ void k_f2bf(const float* __restrict__ in, int n, int which) {
    int i = blockIdx.x * blockDim.x + threadIdx.x;
    if (i >= n) return;
    __nv_bfloat16 v = __float2bfloat16(in[i]);
    if      (which == 0) g_wqkv[i] = v;
    else if (which == 1) g_wproj[i] = v;
    else if (which == 2) g_wfc1[i] = v;
    else                 g_wfc2[i] = v;
}

// ---------------- transpose (B,C,L) -> (B,L,C) ----------------
__global__ void k_transpose_in(const float* __restrict__ x) {
    __shared__ float t[32][33];
    int b = blockIdx.z;
    int c0 = blockIdx.y * 32, l0 = blockIdx.x * 32;
    const float* p = x + (size_t)b * CDIM * LTOK;
    float*       q = g_xt + (size_t)b * CDIM * LTOK;
#pragma unroll
    for (int i = threadIdx.y; i < 32; i += 8)
        t[i][threadIdx.x] = p[(size_t)(c0 + i) * LTOK + l0 + threadIdx.x];
    __syncthreads();
#pragma unroll
    for (int i = threadIdx.y; i < 32; i += 8)
        q[(size_t)(l0 + i) * CDIM + c0 + threadIdx.x] = t[threadIdx.x][i];
}

// ---------------- (B,L,C) -> (B,C,L) final ----------------
__global__ void k_transpose_out(float* __restrict__ out) {
    __shared__ float t[32][33];
    int b = blockIdx.z;
    int l0 = blockIdx.y * 32, c0 = blockIdx.x * 32;
    const float* p = g_z + (size_t)b * CDIM * LTOK;
    float*       q = out + (size_t)b * CDIM * LTOK;
#pragma unroll
    for (int i = threadIdx.y; i < 32; i += 8)
        t[i][threadIdx.x] = p[(size_t)(l0 + i) * CDIM + c0 + threadIdx.x];
    __syncthreads();
#pragma unroll
    for (int i = threadIdx.y; i < 32; i += 8)
        q[(size_t)(c0 + i) * LTOK + l0 + threadIdx.x] = t[threadIdx.x][i];
}

// ---------------- LN1 + shift + window partition (warp per row) ----------------
__global__ void k_ln1_window(const float* __restrict__ g, const float* __restrict__ be) {
    int wid  = (blockIdx.x * blockDim.x + threadIdx.x) >> 5;
    int lane = threadIdx.x & 31;
    if (wid >= MTOK) return;
    int token = winrow_to_token(wid);
    float4 v = reinterpret_cast<const float4*>(g_xt + (size_t)token * CDIM)[lane];
    float s  = v.x + v.y + v.z + v.w;
    float s2 = v.x*v.x + v.y*v.y + v.z*v.z + v.w*v.w;
    s  = warp_sum(s);
    s2 = warp_sum(s2);
    float mean = s * (1.f / CDIM);
    float var  = s2 * (1.f / CDIM) - mean * mean;
    float inv  = rsqrtf(var + 1e-5f);
    float4 gg = reinterpret_cast<const float4*>(g)[lane];
    float4 bb = reinterpret_cast<const float4*>(be)[lane];
    store_bf16x4(g_xw + (size_t)wid * CDIM + lane * 4,
                 (v.x - mean) * inv * gg.x + bb.x,
                 (v.y - mean) * inv * gg.y + bb.y,
                 (v.z - mean) * inv * gg.z + bb.z,
                 (v.w - mean) * inv * gg.w + bb.w);
}

// ---------------- proj-residual (window->token) + LN2 fused ----------------
__global__ void k_res_ln2(const float* __restrict__ g, const float* __restrict__ be) {
    int wid  = (blockIdx.x * blockDim.x + threadIdx.x) >> 5;
    int lane = threadIdx.x & 31;
    if (wid >= MTOK) return;
    int token = winrow_to_token(wid);
    float4 p = reinterpret_cast<const float4*>(g_pout + (size_t)wid   * CDIM)[lane];
    float4 x = reinterpret_cast<const float4*>(g_xt   + (size_t)token * CDIM)[lane];
    float4 y;
    y.x = p.x + x.x; y.y = p.y + x.y; y.z = p.z + x.z; y.w = p.w + x.w;
    reinterpret_cast<float4*>(g_y + (size_t)token * CDIM)[lane] = y;
    float s  = y.x + y.y + y.z + y.w;
    float s2 = y.x*y.x + y.y*y.y + y.z*y.z + y.w*y.w;
    s  = warp_sum(s);
    s2 = warp_sum(s2);
    float mean = s * (1.f / CDIM);
    float var  = s2 * (1.f / CDIM) - mean * mean;
    float inv  = rsqrtf(var + 1e-5f);
    float4 gg = reinterpret_cast<const float4*>(g)[lane];
    float4 bb = reinterpret_cast<const float4*>(be)[lane];
    store_bf16x4(g_h + (size_t)token * CDIM + lane * 4,
                 (y.x - mean) * inv * gg.x + bb.x,
                 (y.y - mean) * inv * gg.y + bb.y,
                 (y.z - mean) * inv * gg.z + bb.z,
                 (y.w - mean) * inv * gg.w + bb.w);
}

// ---------------- attention: one block per (window, head) ----------------
__global__ __launch_bounds__(128) void k_attn(const float* __restrict__ tbl,
                                              const int* __restrict__ relidx) {
    __shared__ float sQ[NTOK * 33];
    __shared__ float sK[NTOK * 33];
    __shared__ float sV[NTOK * 33];
    __shared__ float sS[NTOK * NTOK];
    int bid  = blockIdx.x;
    int win  = bid >> 2;
    int head = bid & 3;
    int tid  = threadIdx.x;

    for (int e = tid; e < NTOK * HD; e += 128) {
        int n = e >> 5, d = e & 31;
        size_t base = ((size_t)win * NTOK + n) * (3 * CDIM) + head * HD + d;
        sQ[n * 33 + d] = g_qkv[base];
        sK[n * 33 + d] = g_qkv[base + CDIM];
        sV[n * 33 + d] = g_qkv[base + 2 * CDIM];
    }
    __syncthreads();

    const float scale = 0.17677669529663687f;  // 32^-0.5
    for (int e = tid; e < NTOK * NTOK; e += 128) {
        int n = e / NTOK, m = e - n * NTOK;
        const float* qp = &sQ[n * 33];
        const float* kp = &sK[m * 33];
        float acc = 0.f;
#pragma unroll
        for (int d = 0; d < HD; d++) acc += qp[d] * kp[d];
        sS[e] = acc * scale + tbl[relidx[e] * HEADS + head];
    }
    __syncthreads();

    if (tid < NTOK) {
        float* row = &sS[tid * NTOK];
        float mx = -1e30f;
#pragma unroll
        for (int m = 0; m < NTOK; m++) mx = fmaxf(mx, row[m]);
        float sum = 0.f;
#pragma unroll
        for (int m = 0; m < NTOK; m++) { float e = expf(row[m] - mx); row[m] = e; sum += e; }
        float r = 1.f / sum;
#pragma unroll
        for (int m = 0; m < NTOK; m++) row[m] *= r;
    }
    __syncthreads();

    for (int e = tid; e < NTOK * HD; e += 128) {
        int n = e >> 5, d = e & 31;
        const float* sr = &sS[n * NTOK];
        float acc = 0.f;
#pragma unroll
        for (int m = 0; m < NTOK; m++) acc += sr[m] * sV[m * 33 + d];
        g_attnout[((size_t)win * NTOK + n) * CDIM + head * HD + d] = __float2bfloat16(acc);
    }
}

// ---------------- bf16 WMMA GEMM: 64x64 tile, K-chunks of 128 ----------------
extern __shared__ __align__(16) unsigned char dynsm[];

template<bool GELU, bool OUT_BF16, bool RES>
__device__ __forceinline__ void gemm_body(
    const __nv_bfloat16* __restrict__ A, const __nv_bfloat16* __restrict__ Bw,
    const float* __restrict__ bias, const float* __restrict__ res,
    float* __restrict__ Cf, __nv_bfloat16* __restrict__ Cb,
    int M, int N, int K)
{
    __nv_bfloat16* sA = reinterpret_cast<__nv_bfloat16*>(dynsm);            // [64][136]
    __nv_bfloat16* sB = sA + 64 * 136;                                      // [128][72]
    float*         sC = reinterpret_cast<float*>(dynsm);                    // [64][68]

    int tid = threadIdx.x;
    int bm = blockIdx.x * 64, bn = blockIdx.y * 64;
    int warp = tid >> 5;
    int wm = (warp >> 1) * 32, wn = (warp & 1) * 32;

    wmma::fragment<wmma::accumulator, 16, 16, 16, float> acc[2][2];
#pragma unroll
    for (int i = 0; i < 2; i++)
#pragma unroll
        for (int j = 0; j < 2; j++) wmma::fill_fragment(acc[i][j], 0.f);

    for (int kc = 0; kc < K; kc += 128) {
#pragma unroll
        for (int it = 0; it < 8; it++) {                 // A chunk: 64 x 128 bf16
            int idx = it * 128 + tid;
            int r = idx >> 4, c16 = idx & 15;
            *reinterpret_cast<uint4*>(&sA[r * 136 + c16 * 8]) =
                *reinterpret_cast<const uint4*>(&A[(size_t)(bm + r) * K + kc + c16 * 8]);
        }
#pragma unroll
        for (int it = 0; it < 8; it++) {                 // B chunk: 128 x 64 bf16
            int idx = it * 128 + tid;
            int r = idx >> 3, c8 = idx & 7;
            *reinterpret_cast<uint4*>(&sB[r * 72 + c8 * 8]) =
                *reinterpret_cast<const uint4*>(&Bw[(size_t)(kc + r) * N + bn + c8 * 8]);
        }
        __syncthreads();
#pragma unroll
        for (int kk = 0; kk < 8; kk++) {
            wmma::fragment<wmma::matrix_a, 16, 16, 16, __nv_bfloat16, wmma::row_major> af[2];
            wmma::fragment<wmma::matrix_b, 16, 16, 16, __nv_bfloat16, wmma::row_major> bf2[2];
            wmma::load_matrix_sync(af[0], &sA[(wm)      * 136 + kk * 16], 136);
            wmma::load_matrix_sync(af[1], &sA[(wm + 16) * 136 + kk * 16], 136);
            wmma::load_matrix_sync(bf2[0], &sB[(kk * 16) * 72 + wn], 72);
            wmma::load_matrix_sync(bf2[1], &sB[(kk * 16) * 72 + wn + 16], 72);
            wmma::mma_sync(acc[0][0], af[0], bf2[0], acc[0][0]);
            wmma::mma_sync(acc[0][1], af[0], bf2[1], acc[0][1]);
            wmma::mma_sync(acc[1][0], af[1], bf2[0], acc[1][0]);
            wmma::mma_sync(acc[1][1], af[1], bf2[1], acc[1][1]);
        }
        __syncthreads();
    }

#pragma unroll
    for (int i = 0; i < 2; i++)
#pragma unroll
        for (int j = 0; j < 2; j++)
            wmma::store_matrix_sync(&sC[(wm + i * 16) * 68 + wn + j * 16], acc[i][j], 68,
                                    wmma::mem_row_major);
    __syncthreads();

    for (int e = tid; e < 64 * 64; e += 128) {
        int r = e >> 6, c = e & 63;
        float v = sC[r * 68 + c] + bias[bn + c];
        if (GELU) v = 0.5f * v * (1.f + erff(v * 0.70710678118654752f));
        size_t o = (size_t)(bm + r) * N + bn + c;
        if (RES) v += res[o];
        if (OUT_BF16) Cb[o] = __float2bfloat16(v);
        else          Cf[o] = v;
    }
}

__global__ __launch_bounds__(128) void k_gemm_qkv(const float* bias) {
    gemm_body<false, false, false>(g_xw, g_wqkv, bias, nullptr, g_qkv, nullptr,
                                   MTOK, 3 * CDIM, CDIM);
}
__global__ __launch_bounds__(128) void k_gemm_proj(const float* bias) {
    gemm_body<false, false, false>(g_attnout, g_wproj, bias, nullptr, g_pout, nullptr,
                                   MTOK, CDIM, CDIM);
}
__global__ __launch_bounds__(128) void k_gemm_fc1(const float* bias) {
    gemm_body<true, true, false>(g_h, g_wfc1, bias, nullptr, nullptr, g_hh,
                                 MTOK, MLP, CDIM);
}
__global__ __launch_bounds__(128) void k_gemm_fc2(const float* bias) {
    gemm_body<false, false, true>(g_hh, g_wfc2, bias, g_y, g_z, nullptr,
                                  MTOK, CDIM, MLP);
}

// ---------------- launch ----------------
extern "C" void kernel_launch(void* const* d_in, const int* in_sizes, int n_in,
                              void* d_out, int out_size) {
    const float* x      = (const float*)d_in[0];
    const float* n1g    = (const float*)d_in[1];
    const float* n1b    = (const float*)d_in[2];
    const float* qkv_w  = (const float*)d_in[3];
    const float* qkv_b  = (const float*)d_in[4];
    const float* tbl    = (const float*)d_in[5];
    const int*   relidx = (const int*)d_in[6];
    const float* proj_w = (const float*)d_in[7];
    const float* proj_b = (const float*)d_in[8];
    const float* n2g    = (const float*)d_in[9];
    const float* n2b    = (const float*)d_in[10];
    const float* fc1_w  = (const float*)d_in[11];
    const float* fc1_b  = (const float*)d_in[12];
    const float* fc2_w  = (const float*)d_in[13];
    const float* fc2_b  = (const float*)d_in[14];
    float* out = (float*)d_out;

    const int GSM = 64 * 136 * 2 + 128 * 72 * 2;  // 35840 bytes dynamic smem

    k_f2bf<<<(CDIM * 3 * CDIM + 255) / 256, 256>>>(qkv_w, CDIM * 3 * CDIM, 0);
    k_f2bf<<<(CDIM * CDIM + 255) / 256, 256>>>(proj_w, CDIM * CDIM, 1);
    k_f2bf<<<(CDIM * MLP + 255) / 256, 256>>>(fc1_w, CDIM * MLP, 2);
    k_f2bf<<<(MLP * CDIM + 255) / 256, 256>>>(fc2_w, MLP * CDIM, 3);

    k_transpose_in<<<dim3(LTOK / 32, CDIM / 32, BB), dim3(32, 8)>>>(x);
    k_ln1_window<<<MTOK / 8, 256>>>(n1g, n1b);
    k_gemm_qkv<<<dim3(MTOK / 64, (3 * CDIM) / 64), 128, GSM>>>(qkv_b);
    k_attn<<<NWIN * HEADS, 128>>>(tbl, relidx);
    k_gemm_proj<<<dim3(MTOK / 64, CDIM / 64), 128, GSM>>>(proj_b);
    k_res_ln2<<<MTOK / 8, 256>>>(n2g, n2b);
    k_gemm_fc1<<<dim3(MTOK / 64, MLP / 64), 128, GSM>>>(fc1_b);
    k_gemm_fc2<<<dim3(MTOK / 64, CDIM / 64), 128, GSM>>>(fc2_b);
    k_transpose_out<<<dim3(CDIM / 32, LTOK / 32, BB), dim3(32, 8)>>>(out);
}

// round 2
// speedup vs baseline: 1.2883x; 1.2883x over previous
#include <cuda_runtime.h>
#include <cuda_bf16.h>
#include <mma.h>

using namespace nvcuda;

// ---------------- problem constants ----------------
#define BB      8
#define CDIM    128
#define HH      112
#define WWID    112
#define LTOK    (HH*WWID)        // 12544
#define MTOK    (BB*LTOK)        // 100352
#define WS      7
#define NTOK    (WS*WS)          // 49
#define NWIN    2048
#define HEADS   4
#define HD      32
#define SHIFT   3
#define MLP     512

// ---------------- scratch (device globals, no allocation) ----------------
__device__ float          g_xt[(size_t)MTOK*CDIM];        // token-major input (shortcut)
__device__ __nv_bfloat16  g_xw[(size_t)MTOK*CDIM];        // LN1 + windowed (GEMM A)
__device__ __nv_bfloat16  g_qkv[(size_t)MTOK*3*CDIM];     // QKV (bf16)
__device__ __nv_bfloat16  g_attnout[(size_t)MTOK*CDIM];   // attention out (window order)
__device__ float          g_y[(size_t)MTOK*CDIM];         // residual 1 (token order)
__device__ __nv_bfloat16  g_h[(size_t)MTOK*CDIM];         // LN2 out (token order)
__device__ __nv_bfloat16  g_hh[(size_t)MTOK*MLP];         // gelu(fc1)

__device__ __nv_bfloat16  g_wqkv[CDIM*3*CDIM];
__device__ __nv_bfloat16  g_wproj[CDIM*CDIM];
__device__ __nv_bfloat16  g_wfc1[CDIM*MLP];
__device__ __nv_bfloat16  g_wfc2[MLP*CDIM];
__device__ float          g_bias[HEADS*NTOK*NTOK];        // precomputed rel-pos bias

// ---------------- helpers ----------------
__device__ __forceinline__ float warp_sum(float v) {
#pragma unroll
    for (int o = 16; o; o >>= 1) v += __shfl_xor_sync(0xffffffffu, v, o);
    return v;
}

// window-order row -> token index (forward mapping, includes shift)
__device__ __forceinline__ int winrow_to_token(int i) {
    int win = i / NTOK, n = i - win * NTOK;
    int b   = win >> 8;
    int wr  = win & 255;
    int wi  = wr >> 4, wj = wr & 15;
    int r   = n / WS,  c = n - r * WS;
    int hs  = wi * WS + r + SHIFT; if (hs >= HH)   hs  -= HH;
    int ws_ = wj * WS + c + SHIFT; if (ws_ >= WWID) ws_ -= WWID;
    return b * LTOK + hs * WWID + ws_;
}

__device__ __forceinline__ void store_bf16x4(__nv_bfloat16* p, float a, float b, float c, float d) {
    __nv_bfloat162 p0 = __floats2bfloat162_rn(a, b);
    __nv_bfloat162 p1 = __floats2bfloat162_rn(c, d);
    uint2 u;
    u.x = *reinterpret_cast<unsigned*>(&p0);
    u.y = *reinterpret_cast<unsigned*>(&p1);
    *reinterpret_cast<uint2*>(p) = u;
}

// ---------------- setup: weights -> bf16, rel-pos bias matrix ----------------
#define W0 (CDIM*3*CDIM)            // 49152
#define W1 (CDIM*CDIM)              // 16384
#define W2 (CDIM*MLP)               // 65536
#define W3 (MLP*CDIM)               // 65536
#define WTOT (W0+W1+W2+W3)          // 196608
#define SETUP_TOT (WTOT + HEADS*NTOK*NTOK)

__global__ void k_setup(const float* __restrict__ qkv_w, const float* __restrict__ proj_w,
                        const float* __restrict__ fc1_w, const float* __restrict__ fc2_w,
                        const float* __restrict__ tbl, const int* __restrict__ relidx) {
    int i = blockIdx.x * blockDim.x + threadIdx.x;
    if (i >= SETUP_TOT) return;
    if (i < W0)                { g_wqkv[i] = __float2bfloat16(qkv_w[i]); return; }
    if (i < W0+W1)             { g_wproj[i-W0] = __float2bfloat16(proj_w[i-W0]); return; }
    if (i < W0+W1+W2)          { g_wfc1[i-W0-W1] = __float2bfloat16(fc1_w[i-W0-W1]); return; }
    if (i < WTOT)              { g_wfc2[i-W0-W1-W2] = __float2bfloat16(fc2_w[i-W0-W1-W2]); return; }
    int j = i - WTOT;                      // [0, 4*2401)
    int h = j / (NTOK*NTOK);
    int e = j - h * (NTOK*NTOK);
    g_bias[h*NTOK*NTOK + e] = tbl[relidx[e]*HEADS + h];
}

// ---------------- fused: transpose (B,C,L)->(B,L,C) + LN1 + window scatter ----------------
// block: 256 threads, 32 consecutive tokens of one batch
__global__ __launch_bounds__(256) void k_ln1t(const float* __restrict__ x,
                                              const float* __restrict__ g,
                                              const float* __restrict__ be) {
    __shared__ float t[CDIM*33];
    int b  = blockIdx.y;
    int l0 = blockIdx.x * 32;
    int tid = threadIdx.x;
    int lane = tid & 31, warp = tid >> 5;

    const float* xb = x + (size_t)b * CDIM * LTOK + l0;
    {
        int l = tid & 31, cg = tid >> 5;
#pragma unroll
        for (int it = 0; it < 16; it++) {
            int c = it * 8 + cg;
            t[c * 33 + l] = xb[(size_t)c * LTOK + l];
        }
    }
    __syncthreads();

    float4 gg = reinterpret_cast<const float4*>(g)[lane];
    float4 bb = reinterpret_cast<const float4*>(be)[lane];
#pragma unroll
    for (int kk = 0; kk < 4; kk++) {
        int tt = warp * 4 + kk;                 // token within block
        int l  = l0 + tt;
        float4 v;
        v.x = t[(lane*4+0)*33 + tt];
        v.y = t[(lane*4+1)*33 + tt];
        v.z = t[(lane*4+2)*33 + tt];
        v.w = t[(lane*4+3)*33 + tt];
        int token = b * LTOK + l;
        reinterpret_cast<float4*>(g_xt + (size_t)token * CDIM)[lane] = v;
        float s  = v.x + v.y + v.z + v.w;
        float s2 = v.x*v.x + v.y*v.y + v.z*v.z + v.w*v.w;
        s  = warp_sum(s); s2 = warp_sum(s2);
        float mean = s * (1.f / CDIM);
        float var  = s2 * (1.f / CDIM) - mean * mean;
        float inv  = rsqrtf(var + 1e-5f);
        // inverse window mapping: token -> window-order row
        int hh = l / WWID, ww = l - hh * WWID;
        int h2 = hh - SHIFT; if (h2 < 0) h2 += HH;
        int w2 = ww - SHIFT; if (w2 < 0) w2 += WWID;
        int win  = (b << 8) + (h2 / WS) * 16 + (w2 / WS);
        int n    = (h2 % WS) * WS + (w2 % WS);
        int wrow = win * NTOK + n;
        store_bf16x4(g_xw + (size_t)wrow * CDIM + lane * 4,
                     (v.x - mean) * inv * gg.x + bb.x,
                     (v.y - mean) * inv * gg.y + bb.y,
                     (v.z - mean) * inv * gg.z + bb.z,
                     (v.w - mean) * inv * gg.w + bb.w);
    }
}

// ---------------- WMMA attention: one block per (window, head) ----------------
__global__ __launch_bounds__(128) void k_attn() {
    __shared__ __nv_bfloat16 sQ[64*40];
    __shared__ __nv_bfloat16 sK[64*40];
    __shared__ __nv_bfloat16 sV[64*40];
    __shared__ float         sS[64*68];
    __shared__ __nv_bfloat16 sP[64*72];
    __shared__ float         srinv[64];

    int bid  = blockIdx.x;
    int win  = bid >> 2;
    int head = bid & 3;
    int tid  = threadIdx.x;
    int warp = tid >> 5;

    // load Q/K/V (rows 49..63 zero-padded), zero sP
    const __nv_bfloat16 zz = __float2bfloat16(0.f);
#pragma unroll
    for (int it = 0; it < 16; it++) {
        int e = it * 128 + tid;            // 2048 = 64*32
        int n = e >> 5, d = e & 31;
        __nv_bfloat16 q = zz, k = zz, v = zz;
        if (n < NTOK) {
            size_t base = ((size_t)win * NTOK + n) * (3*CDIM) + head * HD + d;
            q = g_qkv[base];
            k = g_qkv[base + CDIM];
            v = g_qkv[base + 2*CDIM];
        }
        sQ[n*40 + d] = q;
        sK[n*40 + d] = k;
        sV[n*40 + d] = v;
    }
    for (int e = tid; e < 64*72; e += 128) sP[e] = zz;
    __syncthreads();

    // S = Q * K^T  (64x64x32), warp computes 16x64 stripe
    {
        int wrow = warp * 16;
        wmma::fragment<wmma::accumulator,16,16,16,float> s[4];
#pragma unroll
        for (int j = 0; j < 4; j++) wmma::fill_fragment(s[j], 0.f);
#pragma unroll
        for (int i = 0; i < 2; i++) {
            wmma::fragment<wmma::matrix_a,16,16,16,__nv_bfloat16,wmma::row_major> qa;
            wmma::load_matrix_sync(qa, &sQ[wrow*40 + 16*i], 40);
#pragma unroll
            for (int j = 0; j < 4; j++) {
                wmma::fragment<wmma::matrix_b,16,16,16,__nv_bfloat16,wmma::col_major> kb;
                wmma::load_matrix_sync(kb, &sK[(16*j)*40 + 16*i], 40);
                wmma::mma_sync(s[j], qa, kb, s[j]);
            }
        }
#pragma unroll
        for (int j = 0; j < 4; j++)
            wmma::store_matrix_sync(&sS[wrow*68 + 16*j], s[j], 68, wmma::mem_row_major);
    }
    __syncthreads();

    // softmax rows 0..48 over cols 0..48 (unnormalized P, defer 1/sum)
    if (tid < NTOK) {
        const float scale = 0.17677669529663687f;
        const float* brow = &g_bias[head*NTOK*NTOK + tid*NTOK];
        float* srow = &sS[tid*68];
        float mx = -1e30f;
#pragma unroll
        for (int m = 0; m < NTOK; m++) {
            float v = srow[m] * scale + brow[m];
            srow[m] = v;
            mx = fmaxf(mx, v);
        }
        float sum = 0.f;
        __nv_bfloat16* prow = &sP[tid*72];
#pragma unroll
        for (int m = 0; m < NTOK; m++) {
            float e = expf(srow[m] - mx);
            sum += e;
            prow[m] = __float2bfloat16(e);
        }
        srinv[tid] = 1.f / sum;
    }
    __syncthreads();

    // O = P * V  (64x32x64)
    {
        int wrow = warp * 16;
        wmma::fragment<wmma::accumulator,16,16,16,float> o[2];
#pragma unroll
        for (int j = 0; j < 2; j++) wmma::fill_fragment(o[j], 0.f);
#pragma unroll
        for (int i = 0; i < 4; i++) {
            wmma::fragment<wmma::matrix_a,16,16,16,__nv_bfloat16,wmma::row_major> pa;
            wmma::load_matrix_sync(pa, &sP[wrow*72 + 16*i], 72);
#pragma unroll
            for (int j = 0; j < 2; j++) {
                wmma::fragment<wmma::matrix_b,16,16,16,__nv_bfloat16,wmma::row_major> vb;
                wmma::load_matrix_sync(vb, &sV[(16*i)*40 + 16*j], 40);
                wmma::mma_sync(o[j], pa, vb, o[j]);
            }
        }
        __syncthreads();   // sS free now
#pragma unroll
        for (int j = 0; j < 2; j++)
            wmma::store_matrix_sync(&sS[wrow*68 + 16*j], o[j], 68, wmma::mem_row_major);
    }
    __syncthreads();

#pragma unroll
    for (int it = 0; it < 13; it++) {
        int e = it * 128 + tid;
        if (e < NTOK * HD) {
            int n = e >> 5, d = e & 31;
            g_attnout[((size_t)win * NTOK + n) * CDIM + head * HD + d] =
                __float2bfloat16(sS[n*68 + d] * srinv[n]);
        }
    }
}

// ---------------- big-tile WMMA GEMM: 128xN, A resident, fused epilogues ----------------
// EPI: 0 = QKV (bias -> bf16), 1 = PROJ (bias + residual + LN2),
//      2 = FC1 (bias + gelu -> bf16), 3 = FC2 (bias + residual -> transposed fp32 out)
template<int NT, int KT, int EPI>
__device__ __forceinline__ void gemm128(
    const __nv_bfloat16* __restrict__ A,
    const __nv_bfloat16* __restrict__ Bw,
    const float* __restrict__ bias,
    float* __restrict__ outf,
    const float* __restrict__ ln_g,
    const float* __restrict__ ln_b)
{
    extern __shared__ __align__(16) unsigned char dyn[];
    __nv_bfloat16* sA = reinterpret_cast<__nv_bfloat16*>(dyn);           // [128][136]
    __nv_bfloat16* sB = sA + 128*136;                                    // [128][136]
    float*         sC = reinterpret_cast<float*>(dyn + 128*136*2);       // [64][132] alias sB

    const int tid  = threadIdx.x;
    const int warp = tid >> 5, lane = tid & 31;
    const int bm   = blockIdx.x * 128;
    const int wm   = (warp & 3) * 32, wn = (warp >> 2) * 64;

#pragma unroll
    for (int nc = 0; nc < NT/128; nc++) {
        wmma::fragment<wmma::accumulator,16,16,16,float> acc[2][4];
#pragma unroll
        for (int i = 0; i < 2; i++)
#pragma unroll
            for (int j = 0; j < 4; j++) wmma::fill_fragment(acc[i][j], 0.f);

#pragma unroll
        for (int kc = 0; kc < KT; kc += 128) {
            if (KT > 128 || nc == 0) {
#pragma unroll
                for (int it = 0; it < 8; it++) {
                    int idx = it * 256 + tid;
                    int r = idx >> 4, c = idx & 15;
                    *reinterpret_cast<uint4*>(&sA[r*136 + c*8]) =
                        *reinterpret_cast<const uint4*>(&A[(size_t)(bm + r) * KT + kc + c*8]);
                }
            }
#pragma unroll
            for (int it = 0; it < 8; it++) {
                int idx = it * 256 + tid;
                int r = idx >> 4, c = idx & 15;
                *reinterpret_cast<uint4*>(&sB[r*136 + c*8]) =
                    *reinterpret_cast<const uint4*>(&Bw[(size_t)(kc + r) * NT + nc*128 + c*8]);
            }
            __syncthreads();
#pragma unroll
            for (int kk = 0; kk < 8; kk++) {
                wmma::fragment<wmma::matrix_a,16,16,16,__nv_bfloat16,wmma::row_major> af[2];
#pragma unroll
                for (int i = 0; i < 2; i++)
                    wmma::load_matrix_sync(af[i], &sA[(wm + 16*i)*136 + kk*16], 136);
#pragma unroll
                for (int j = 0; j < 4; j++) {
                    wmma::fragment<wmma::matrix_b,16,16,16,__nv_bfloat16,wmma::row_major> bf;
                    wmma::load_matrix_sync(bf, &sB[(kk*16)*136 + wn + 16*j], 136);
#pragma unroll
                    for (int i = 0; i < 2; i++)
                        wmma::mma_sync(acc[i][j], af[i], bf, acc[i][j]);
                }
            }
            __syncthreads();
        }

        // ---- epilogue, two 64-row halves staged in sC (aliases sB) ----
#pragma unroll
        for (int h = 0; h < 2; h++) {
            if (((warp & 3) >> 1) == h) {
                int wl = wm - 64*h;
#pragma unroll
                for (int i = 0; i < 2; i++)
#pragma unroll
                    for (int j = 0; j < 4; j++)
                        wmma::store_matrix_sync(&sC[(wl + 16*i)*132 + wn + 16*j],
                                                acc[i][j], 132, wmma::mem_row_major);
            }
            __syncthreads();

            if (EPI == 0) {                       // QKV
                for (int e = tid; e < 64*128; e += 256) {
                    int r = e >> 7, c = e & 127;
                    float v = sC[r*132 + c] + bias[nc*128 + c];
                    g_qkv[(size_t)(bm + 64*h + r)*(3*CDIM) + nc*128 + c] = __float2bfloat16(v);
                }
            } else if (EPI == 2) {                // FC1 + gelu
                for (int e = tid; e < 64*128; e += 256) {
                    int r = e >> 7, c = e & 127;
                    float v = sC[r*132 + c] + bias[nc*128 + c];
                    v = 0.5f * v * (1.f + erff(v * 0.70710678118654752f));
                    g_hh[(size_t)(bm + 64*h + r)*MLP + nc*128 + c] = __float2bfloat16(v);
                }
            } else if (EPI == 1) {                // PROJ + residual + LN2
                float4 pb = reinterpret_cast<const float4*>(bias)[lane];
                float4 gg = reinterpret_cast<const float4*>(ln_g)[lane];
                float4 lb = reinterpret_cast<const float4*>(ln_b)[lane];
#pragma unroll
                for (int rr = warp; rr < 64; rr += 8) {
                    float4 v = *reinterpret_cast<float4*>(&sC[rr*132 + lane*4]);
                    int token = winrow_to_token(bm + 64*h + rr);
                    float4 x = reinterpret_cast<const float4*>(g_xt + (size_t)token*CDIM)[lane];
                    float4 y;
                    y.x = v.x + pb.x + x.x;  y.y = v.y + pb.y + x.y;
                    y.z = v.z + pb.z + x.z;  y.w = v.w + pb.w + x.w;
                    reinterpret_cast<float4*>(g_y + (size_t)token*CDIM)[lane] = y;
                    float s  = y.x + y.y + y.z + y.w;
                    float s2 = y.x*y.x + y.y*y.y + y.z*y.z + y.w*y.w;
                    s = warp_sum(s); s2 = warp_sum(s2);
                    float mean = s * (1.f / CDIM);
                    float var  = s2 * (1.f / CDIM) - mean * mean;
                    float inv  = rsqrtf(var + 1e-5f);
                    store_bf16x4(g_h + (size_t)token*CDIM + lane*4,
                                 (y.x - mean) * inv * gg.x + lb.x,
                                 (y.y - mean) * inv * gg.y + lb.y,
                                 (y.z - mean) * inv * gg.z + lb.z,
                                 (y.w - mean) * inv * gg.w + lb.w);
                }
            } else {                              // FC2 + residual + transposed store
                int row0 = bm + 64*h;
                for (int e = tid; e < 64*128; e += 256) {
                    int r = e >> 7, c = e & 127;
                    sC[r*132 + c] += bias[c] + g_y[(size_t)(row0 + r)*CDIM + c];
                }
                __syncthreads();
                int b  = row0 / LTOK;
                int l0 = row0 - b * LTOK;
                float* ob = outf + (size_t)b * CDIM * LTOK + l0;
                int l = tid & 63, cb = tid >> 6;
#pragma unroll
                for (int it = 0; it < 32; it++) {
                    int c = it * 4 + cb;
                    ob[(size_t)c * LTOK + l] = sC[l*132 + c];
                }
            }
            __syncthreads();
        }
    }
}

__global__ __launch_bounds__(256) void k_gemm_qkv(const float* bias) {
    gemm128<384,128,0>(g_xw, g_wqkv, bias, nullptr, nullptr, nullptr);
}
__global__ __launch_bounds__(256) void k_gemm_proj(const float* bias, const float* g, const float* b2) {
    gemm128<128,128,1>(g_attnout, g_wproj, bias, nullptr, g, b2);
}
__global__ __launch_bounds__(256) void k_gemm_fc1(const float* bias) {
    gemm128<512,128,2>(g_h, g_wfc1, bias, nullptr, nullptr, nullptr);
}
__global__ __launch_bounds__(256) void k_gemm_fc2(const float* bias, float* out) {
    gemm128<128,512,3>(g_hh, g_wfc2, bias, out, nullptr, nullptr);
}

// ---------------- launch ----------------
extern "C" void kernel_launch(void* const* d_in, const int* in_sizes, int n_in,
                              void* d_out, int out_size) {
    const float* x      = (const float*)d_in[0];
    const float* n1g    = (const float*)d_in[1];
    const float* n1b    = (const float*)d_in[2];
    const float* qkv_w  = (const float*)d_in[3];
    const float* qkv_b  = (const float*)d_in[4];
    const float* tbl    = (const float*)d_in[5];
    const int*   relidx = (const int*)d_in[6];
    const float* proj_w = (const float*)d_in[7];
    const float* proj_b = (const float*)d_in[8];
    const float* n2g    = (const float*)d_in[9];
    const float* n2b    = (const float*)d_in[10];
    const float* fc1_w  = (const float*)d_in[11];
    const float* fc1_b  = (const float*)d_in[12];
    const float* fc2_w  = (const float*)d_in[13];
    const float* fc2_b  = (const float*)d_in[14];
    float* out = (float*)d_out;

    const int GSM = 128*136*2*2;   // 69632 B dynamic smem
    cudaFuncSetAttribute(k_gemm_qkv,  cudaFuncAttributeMaxDynamicSharedMemorySize, GSM);
    cudaFuncSetAttribute(k_gemm_proj, cudaFuncAttributeMaxDynamicSharedMemorySize, GSM);
    cudaFuncSetAttribute(k_gemm_fc1,  cudaFuncAttributeMaxDynamicSharedMemorySize, GSM);
    cudaFuncSetAttribute(k_gemm_fc2,  cudaFuncAttributeMaxDynamicSharedMemorySize, GSM);

    k_setup<<<(SETUP_TOT + 255)/256, 256>>>(qkv_w, proj_w, fc1_w, fc2_w, tbl, relidx);
    k_ln1t<<<dim3(LTOK/32, BB), 256>>>(x, n1g, n1b);
    k_gemm_qkv<<<MTOK/128, 256, GSM>>>(qkv_b);
    k_attn<<<NWIN*HEADS, 128>>>();
    k_gemm_proj<<<MTOK/128, 256, GSM>>>(proj_b, n2g, n2b);
    k_gemm_fc1<<<MTOK/128, 256, GSM>>>(fc1_b);
    k_gemm_fc2<<<MTOK/128, 256, GSM>>>(fc2_b, out);
}